// round 16
// baseline (speedup 1.0000x reference)
#include <cuda_runtime.h>

#define VOCAB 32
#define UTT_LEN 16
#define NTYPES 5
#define MPT 10
#define SUPPORT 100000
#define BATCH 2048

#define NS 16                            // support chunks
#define CHUNK (SUPPORT / NS)             // 6250
#define TPB 256
#define FULL_ITERS (CHUNK / TPB)         // 24
#define TAIL (CHUNK - FULL_ITERS * TPB)  // 106
#define NGROUPS (BATCH / 32)             // 64
#define NBLKS (NS * NGROUPS)             // 1024 knn blocks

#define ENTRIES (SUPPORT * UTT_LEN)      // 1,600,000 (divisible by 32)

// scratch (no cudaMalloc allowed)
__device__ unsigned char g_packed[ENTRIES];           // token*4 per position
__device__ unsigned int  g_keys[BATCH];               // (cnt<<17)|(131071-row)
__device__ unsigned int  g_done;                      // knn block-completion ctr

// PDL: wait for the full upstream grid (memory-visible) — sm_90+.
__device__ __forceinline__ void griddep_wait() {
    asm volatile("griddepcontrol.wait;" ::: "memory");
}

// ---------------------------------------------------------------------------
// Kernel 1: zero keys + reset done-counter + decode one-hot support ->
// packed tokens (x4). R3/R14-exact memory behavior (33.2us, DRAM 79% =
// streaming wall). Plain launch (measured best in R14).
// ---------------------------------------------------------------------------
__global__ void __launch_bounds__(256) decode_kernel(
        const float* __restrict__ support) {
    const unsigned tid  = blockIdx.x * blockDim.x + threadIdx.x;
    const unsigned lane = threadIdx.x & 31;

    if (tid < BATCH) g_keys[tid] = 0u;
    if (tid == BATCH) g_done = 0u;                // reset for this replay

    const unsigned gwarp = tid >> 5;              // global warp id
    const unsigned base  = gwarp * 32;            // first entry of this warp
    if (base >= ENTRIES) return;

    const float4* p = reinterpret_cast<const float4*>(support) + (size_t)base * 8;
    const int myr = (int)(lane >> 2);             // round holding my entry
    const int sh  = (int)(lane & 3) * 8;          // byte of my entry in ballots

    unsigned mysub = 0;
#pragma unroll
    for (int r = 0; r < 8; r++) {
        float4 v = __ldcs(p + r * 32 + lane);     // 512B contiguous, streaming
        unsigned bx = __ballot_sync(0xffffffffu, v.x != 0.0f);
        unsigned by = __ballot_sync(0xffffffffu, v.y != 0.0f);
        unsigned bz = __ballot_sync(0xffffffffu, v.z != 0.0f);
        unsigned bw = __ballot_sync(0xffffffffu, v.w != 0.0f);
        unsigned sub = ((bx >> sh) & 0xFFu)
                     | (((by >> sh) & 0xFFu) << 8)
                     | (((bz >> sh) & 0xFFu) << 16)
                     | (((bw >> sh) & 0xFFu) << 24);
        if (r == myr) mysub = sub;
    }
    int b = __ffs(mysub) - 1;                     // bit index in submask
    int v = ((b & 7) << 2) | (b >> 3);            // vocab token
    g_packed[base + lane] = (unsigned char)(v << 2);  // pre-scaled x4
}

// ---------------------------------------------------------------------------
// Kernel 2: bit-sliced match counting + argmax (R3-exact math) + FUSED
// OUTPUT: the last block to finish (g_done pattern) gathers meanings and
// emits the one-hot output, eliminating the third kernel launch entirely.
// PDL: the preamble (dtype detect + ballot table build + syncthreads) runs
// while the decode grid drains.
// ---------------------------------------------------------------------------
__device__ __forceinline__ void fa(unsigned a, unsigned b, unsigned c,
                                   unsigned& s, unsigned& cy) {
    s  = a ^ b ^ c;                       // LOP3 0x96
    cy = (a & b) | (a & c) | (b & c);     // LOP3 0xE8
}
__device__ __forceinline__ void ha(unsigned a, unsigned b,
                                   unsigned& s, unsigned& cy) {
    s = a ^ b; cy = a & b;
}

__global__ void __launch_bounds__(TPB) knn_kernel(const void* __restrict__ uttsv,
                                                  const void* __restrict__ meanv,
                                                  float* __restrict__ out) {
    __shared__ unsigned tbl[UTT_LEN * VOCAB];  // tbl[m*32+v]: bit q = (tok_q[m]==v)
    __shared__ bool slast;

    const unsigned tid   = threadIdx.x;
    const unsigned lane  = tid & 31;
    const unsigned warp  = tid >> 5;
    const unsigned chunk = blockIdx.x;
    const unsigned group = blockIdx.y;

    // ---- PREAMBLE (no dependence on decode; overlaps decode tail) ----
    // per-warp dtype detect: int64 (LE) -> odd words of first 128 pairs are 0
    const int* u32p = (const int*)uttsv;
    const long long* u64p = (const long long*)uttsv;
    {
        bool nz = false;
#pragma unroll
        for (int r = 0; r < 4; r++) nz |= (u32p[(lane * 4 + r) * 2 + 1] != 0);
        const bool is64 = (__ballot_sync(0xffffffffu, nz) == 0);

        const unsigned col = group * 32 + lane;
#pragma unroll
        for (int mm = 0; mm < 2; mm++) {
            int m = (int)(warp * 2 + mm);
            int tok = is64 ? (int)u64p[(size_t)m * BATCH + col]
                           : u32p[(size_t)m * BATCH + col];
#pragma unroll
            for (int v = 0; v < VOCAB; v++) {
                unsigned bm = __ballot_sync(0xffffffffu, tok == v);
                if (lane == (unsigned)v) tbl[m * VOCAB + v] = bm;
            }
        }
    }
    __syncthreads();

    // ---- wait for decode grid (g_packed + zeroed g_keys/g_done visible) ----
    griddep_wait();

    const unsigned rowBase = chunk * CHUNK;
    const uint4* pk = reinterpret_cast<const uint4*>(g_packed) + rowBase + tid;
    const char* tbc = (const char*)tbl;

    unsigned mx0 = 0, mx1 = 0, mx2 = 0, mx3 = 0, mx4 = 0;
    unsigned b0 = 0, b1 = 0, b2 = 0, b3 = 0, b4 = 0;

#define STEP(I)                                                                   \
    do {                                                                          \
        uint4 pw = pk[(I) * TPB];                                                 \
        unsigned l0  = *(const unsigned*)(tbc + 0 * 128  + __byte_perm(pw.x, 0, 0x4440)); \
        unsigned l1  = *(const unsigned*)(tbc + 1 * 128  + __byte_perm(pw.x, 0, 0x4441)); \
        unsigned l2  = *(const unsigned*)(tbc + 2 * 128  + __byte_perm(pw.x, 0, 0x4442)); \
        unsigned l3  = *(const unsigned*)(tbc + 3 * 128  + __byte_perm(pw.x, 0, 0x4443)); \
        unsigned l4  = *(const unsigned*)(tbc + 4 * 128  + __byte_perm(pw.y, 0, 0x4440)); \
        unsigned l5  = *(const unsigned*)(tbc + 5 * 128  + __byte_perm(pw.y, 0, 0x4441)); \
        unsigned l6  = *(const unsigned*)(tbc + 6 * 128  + __byte_perm(pw.y, 0, 0x4442)); \
        unsigned l7  = *(const unsigned*)(tbc + 7 * 128  + __byte_perm(pw.y, 0, 0x4443)); \
        unsigned l8  = *(const unsigned*)(tbc + 8 * 128  + __byte_perm(pw.z, 0, 0x4440)); \
        unsigned l9  = *(const unsigned*)(tbc + 9 * 128  + __byte_perm(pw.z, 0, 0x4441)); \
        unsigned l10 = *(const unsigned*)(tbc + 10 * 128 + __byte_perm(pw.z, 0, 0x4442)); \
        unsigned l11 = *(const unsigned*)(tbc + 11 * 128 + __byte_perm(pw.z, 0, 0x4443)); \
        unsigned l12 = *(const unsigned*)(tbc + 12 * 128 + __byte_perm(pw.w, 0, 0x4440)); \
        unsigned l13 = *(const unsigned*)(tbc + 13 * 128 + __byte_perm(pw.w, 0, 0x4441)); \
        unsigned l14 = *(const unsigned*)(tbc + 14 * 128 + __byte_perm(pw.w, 0, 0x4442)); \
        unsigned l15 = *(const unsigned*)(tbc + 15 * 128 + __byte_perm(pw.w, 0, 0x4443)); \
        unsigned s0, c0, s1, c1, s2, c2, s3, c3, s4, c4;                          \
        fa(l0, l1, l2, s0, c0);                                                   \
        fa(l3, l4, l5, s1, c1);                                                   \
        fa(l6, l7, l8, s2, c2);                                                   \
        fa(l9, l10, l11, s3, c3);                                                 \
        fa(l12, l13, l14, s4, c4);                                                \
        unsigned t0, d0, t1, d1;                                                  \
        fa(s0, s1, s2, t0, d0);                                                   \
        fa(s3, s4, l15, t1, d1);                                                  \
        unsigned n0, e0; ha(t0, t1, n0, e0);                                      \
        unsigned f0, g0, f1, g1, f2, g2;                                          \
        fa(c0, c1, c2, f0, g0);                                                   \
        fa(c3, c4, d0, f1, g1);                                                   \
        fa(f0, f1, d1, f2, g2);                                                   \
        unsigned n1, g3; ha(f2, e0, n1, g3);                                      \
        unsigned h0, k0; fa(g0, g1, g2, h0, k0);                                  \
        unsigned n2, k1; ha(h0, g3, n2, k1);                                      \
        unsigned n3, n4; ha(k0, k1, n3, n4);                                      \
        unsigned gt = n0 & ~mx0;                                                  \
        gt = (n1 & ~mx1) | (~(n1 ^ mx1) & gt);                                    \
        gt = (n2 & ~mx2) | (~(n2 ^ mx2) & gt);                                    \
        gt = (n3 & ~mx3) | (~(n3 ^ mx3) & gt);                                    \
        gt = (n4 & ~mx4) | (~(n4 ^ mx4) & gt);                                    \
        mx0 = (n0 & gt) | (mx0 & ~gt);                                            \
        mx1 = (n1 & gt) | (mx1 & ~gt);                                            \
        mx2 = (n2 & gt) | (mx2 & ~gt);                                            \
        mx3 = (n3 & gt) | (mx3 & ~gt);                                            \
        mx4 = (n4 & gt) | (mx4 & ~gt);                                            \
        if ((I) & 1)  b0 |= gt; else b0 &= ~gt;                                   \
        if ((I) & 2)  b1 |= gt; else b1 &= ~gt;                                   \
        if ((I) & 4)  b2 |= gt; else b2 &= ~gt;                                   \
        if ((I) & 8)  b3 |= gt; else b3 &= ~gt;                                   \
        if ((I) & 16) b4 |= gt; else b4 &= ~gt;                                   \
    } while (0)

    STEP(0);  STEP(1);  STEP(2);  STEP(3);  STEP(4);  STEP(5);
    STEP(6);  STEP(7);  STEP(8);  STEP(9);  STEP(10); STEP(11);
    STEP(12); STEP(13); STEP(14); STEP(15); STEP(16); STEP(17);
    STEP(18); STEP(19); STEP(20); STEP(21); STEP(22); STEP(23);
    if (tid < TAIL) STEP(24);
#undef STEP

    // Materialize full row planes: row = tid (8 bits) | iter (5 bits).
    unsigned mx[5] = {mx0, mx1, mx2, mx3, mx4};
    unsigned bi[13];
#pragma unroll
    for (int p = 0; p < 8; p++) bi[p] = (tid & (1u << p)) ? 0xffffffffu : 0u;
    bi[8] = b0; bi[9] = b1; bi[10] = b2; bi[11] = b3; bi[12] = b4;

    // Warp butterfly merge of (cnt desc, row asc), bit-sliced.
#pragma unroll
    for (int k = 1; k < 32; k <<= 1) {
        unsigned o[5], q[13];
#pragma unroll
        for (int p = 0; p < 5; p++)  o[p] = __shfl_xor_sync(0xffffffffu, mx[p], k);
#pragma unroll
        for (int p = 0; p < 13; p++) q[p] = __shfl_xor_sync(0xffffffffu, bi[p], k);
        unsigned gtc = mx[0] & ~o[0];
#pragma unroll
        for (int p = 1; p < 5; p++)
            gtc = (mx[p] & ~o[p]) | (~(mx[p] ^ o[p]) & gtc);
        unsigned orx = 0;
#pragma unroll
        for (int p = 0; p < 5; p++) orx |= mx[p] ^ o[p];    // ~orx = counts equal
        unsigned lt = ~bi[0] & q[0];
#pragma unroll
        for (int p = 1; p < 13; p++)
            lt = (~bi[p] & q[p]) | (~(bi[p] ^ q[p]) & lt);  // my row < partner row
        unsigned tm = gtc | (lt & ~orx);                    // keep mine
#pragma unroll
        for (int p = 0; p < 5; p++)  mx[p] = (mx[p] & tm) | (o[p] & ~tm);
#pragma unroll
        for (int p = 0; p < 13; p++) bi[p] = (bi[p] & tm) | (q[p] & ~tm);
    }

    // lane q extracts query q's (cnt,row) from the merged planes
    unsigned cnt = 0, lr = 0;
#pragma unroll
    for (int p = 0; p < 5; p++)  cnt |= ((mx[p] >> lane) & 1u) << p;
#pragma unroll
    for (int p = 0; p < 13; p++) lr  |= ((bi[p] >> lane) & 1u) << p;
    unsigned row = rowBase + lr;
    unsigned key = (cnt << 17) | (131071u - row);
    atomicMax(&g_keys[group * 32 + lane], key);

    // ---- FUSED OUTPUT: last finishing block emits the one-hot result ----
    __threadfence();                       // publish my atomicMax before count
    __syncthreads();
    if (tid == 0) slast = (atomicAdd(&g_done, 1u) == (unsigned)(NBLKS - 1));
    __syncthreads();
    if (!slast) return;
    __threadfence();                       // acquire: all blocks' maxes visible

    // meanings dtype detect (per warp; same LE-zero-word trick)
    const int* m32 = (const int*)meanv;
    bool nzd = false;
#pragma unroll
    for (int r = 0; r < 4; r++) nzd |= (m32[(lane * 4 + r) * 2 + 1] != 0);
    const bool m64 = (__ballot_sync(0xffffffffu, nzd) == 0);

    for (int q = (int)tid; q < BATCH; q += TPB) {
        unsigned k2 = g_keys[q];           // plain load: L1 fresh this kernel
        int wrow = 131071 - (int)(k2 & 0x1FFFFu);
        int m[NTYPES];
#pragma unroll
        for (int t = 0; t < NTYPES; t++)
            m[t] = m64 ? (int)((const long long*)meanv)[(size_t)wrow * NTYPES + t]
                       : m32[(size_t)wrow * NTYPES + t];
        float2* o = reinterpret_cast<float2*>(out + (size_t)q * NTYPES * MPT);
#pragma unroll
        for (int e = 0; e < (NTYPES * MPT) / 2; e++) {
            const int e0 = 2 * e, e1 = 2 * e + 1;
            float2 v;
            v.x = (m[e0 / MPT] == e0 % MPT) ? 1.0f : 0.0f;
            v.y = (m[e1 / MPT] == e1 % MPT) ? 1.0f : 0.0f;
            o[e] = v;
        }
    }
}

extern "C" void kernel_launch(void* const* d_in, const int* in_sizes, int n_in,
                              void* d_out, int out_size) {
    const void*  utts     = d_in[0];                 // [16,2048] int64/int32
    const float* support  = (const float*)d_in[1];   // [100000,512] fp32 one-hot
    const void*  meanings = (const void*)d_in[2];    // [100000,5] int64/int32
    float* out = (float*)d_out;                      // [2048,5,10] fp32

    decode_kernel<<<(ENTRIES / 32 + 7) / 8, 256>>>(support);

    // knn (+fused output) with PDL: preamble overlaps decode tail
    {
        cudaLaunchConfig_t cfg = {};
        cfg.gridDim  = dim3(NS, NGROUPS);            // (16,64) = 1024 blocks
        cfg.blockDim = dim3(TPB);
        cfg.stream   = 0;
        cudaLaunchAttribute a[1];
        a[0].id = cudaLaunchAttributeProgrammaticStreamSerialization;
        a[0].val.programmaticStreamSerializationAllowed = 1;
        cfg.attrs = a;
        cfg.numAttrs = 1;
        cudaLaunchKernelEx(&cfg, knn_kernel, utts, meanings, out);
    }
}

// round 17
// speedup vs baseline: 1.3852x; 1.3852x over previous
#include <cuda_runtime.h>

#define VOCAB 32
#define UTT_LEN 16
#define NTYPES 5
#define MPT 10
#define SUPPORT 100000
#define BATCH 2048

#define NS 16                            // support chunks
#define CHUNK (SUPPORT / NS)             // 6250
#define TPB 256
#define FULL_ITERS (CHUNK / TPB)         // 24
#define TAIL (CHUNK - FULL_ITERS * TPB)  // 106
#define NGROUPS (BATCH / 32)             // 64

#define ENTRIES (SUPPORT * UTT_LEN)      // 1,600,000 (divisible by 32)

// scratch (no cudaMalloc allowed)
__device__ unsigned char g_packed[ENTRIES];           // token*4 per position
__device__ unsigned int  g_keys[BATCH];               // (cnt<<17)|(131071-row)

// PDL: wait for the full upstream grid (memory-visible) — sm_90+.
__device__ __forceinline__ void griddep_wait() {
    asm volatile("griddepcontrol.wait;" ::: "memory");
}

// ---------------------------------------------------------------------------
// Kernel 1: zero keys + decode one-hot support -> packed tokens (x4).
// R3-exact memory behavior (33.2us, DRAM 79% = compulsory-traffic wall).
// Plain launch — decode must own the whole chip (R4/R16 lesson: anything
// that lets downstream blocks become co-resident under decode regresses).
// ---------------------------------------------------------------------------
__global__ void __launch_bounds__(256) decode_kernel(
        const float* __restrict__ support) {
    const unsigned tid  = blockIdx.x * blockDim.x + threadIdx.x;
    const unsigned lane = threadIdx.x & 31;

    if (tid < BATCH) g_keys[tid] = 0u;

    const unsigned gwarp = tid >> 5;              // global warp id
    const unsigned base  = gwarp * 32;            // first entry of this warp
    if (base >= ENTRIES) return;

    const float4* p = reinterpret_cast<const float4*>(support) + (size_t)base * 8;
    const int myr = (int)(lane >> 2);             // round holding my entry
    const int sh  = (int)(lane & 3) * 8;          // byte of my entry in ballots

    unsigned mysub = 0;
#pragma unroll
    for (int r = 0; r < 8; r++) {
        float4 v = __ldcs(p + r * 32 + lane);     // 512B contiguous, streaming
        unsigned bx = __ballot_sync(0xffffffffu, v.x != 0.0f);
        unsigned by = __ballot_sync(0xffffffffu, v.y != 0.0f);
        unsigned bz = __ballot_sync(0xffffffffu, v.z != 0.0f);
        unsigned bw = __ballot_sync(0xffffffffu, v.w != 0.0f);
        unsigned sub = ((bx >> sh) & 0xFFu)
                     | (((by >> sh) & 0xFFu) << 8)
                     | (((bz >> sh) & 0xFFu) << 16)
                     | (((bw >> sh) & 0xFFu) << 24);
        if (r == myr) mysub = sub;
    }
    int b = __ffs(mysub) - 1;                     // bit index in submask
    int v = ((b & 7) << 2) | (b >> 3);            // vocab token
    g_packed[base + lane] = (unsigned char)(v << 2);  // pre-scaled x4
}

// ---------------------------------------------------------------------------
// Kernel 2: bit-sliced match counting + argmax (R3-exact math). PDL: the
// preamble (dtype detect + ballot table build + syncthreads) runs while the
// decode grid drains; griddep_wait() precedes any g_packed/g_keys access.
// ---------------------------------------------------------------------------
__device__ __forceinline__ void fa(unsigned a, unsigned b, unsigned c,
                                   unsigned& s, unsigned& cy) {
    s  = a ^ b ^ c;                       // LOP3 0x96
    cy = (a & b) | (a & c) | (b & c);     // LOP3 0xE8
}
__device__ __forceinline__ void ha(unsigned a, unsigned b,
                                   unsigned& s, unsigned& cy) {
    s = a ^ b; cy = a & b;
}

__global__ void __launch_bounds__(TPB) knn_kernel(const void* __restrict__ uttsv) {
    __shared__ unsigned tbl[UTT_LEN * VOCAB];  // tbl[m*32+v]: bit q = (tok_q[m]==v)

    const unsigned tid   = threadIdx.x;
    const unsigned lane  = tid & 31;
    const unsigned warp  = tid >> 5;
    const unsigned chunk = blockIdx.x;
    const unsigned group = blockIdx.y;

    // ---- PREAMBLE (no dependence on decode) ----
    // per-warp dtype detect: int64 (LE) -> odd words of first 128 pairs are 0
    const int* u32p = (const int*)uttsv;
    const long long* u64p = (const long long*)uttsv;
    {
        bool nz = false;
#pragma unroll
        for (int r = 0; r < 4; r++) nz |= (u32p[(lane * 4 + r) * 2 + 1] != 0);
        const bool is64 = (__ballot_sync(0xffffffffu, nz) == 0);

        const unsigned col = group * 32 + lane;
#pragma unroll
        for (int mm = 0; mm < 2; mm++) {
            int m = (int)(warp * 2 + mm);
            int tok = is64 ? (int)u64p[(size_t)m * BATCH + col]
                           : u32p[(size_t)m * BATCH + col];
#pragma unroll
            for (int v = 0; v < VOCAB; v++) {
                unsigned bm = __ballot_sync(0xffffffffu, tok == v);
                if (lane == (unsigned)v) tbl[m * VOCAB + v] = bm;
            }
        }
    }
    __syncthreads();

    // ---- wait for decode grid (g_packed + zeroed g_keys visible) ----
    griddep_wait();

    const unsigned rowBase = chunk * CHUNK;
    const uint4* pk = reinterpret_cast<const uint4*>(g_packed) + rowBase + tid;
    const char* tbc = (const char*)tbl;

    unsigned mx0 = 0, mx1 = 0, mx2 = 0, mx3 = 0, mx4 = 0;
    unsigned b0 = 0, b1 = 0, b2 = 0, b3 = 0, b4 = 0;

#define STEP(I)                                                                   \
    do {                                                                          \
        uint4 pw = pk[(I) * TPB];                                                 \
        unsigned l0  = *(const unsigned*)(tbc + 0 * 128  + __byte_perm(pw.x, 0, 0x4440)); \
        unsigned l1  = *(const unsigned*)(tbc + 1 * 128  + __byte_perm(pw.x, 0, 0x4441)); \
        unsigned l2  = *(const unsigned*)(tbc + 2 * 128  + __byte_perm(pw.x, 0, 0x4442)); \
        unsigned l3  = *(const unsigned*)(tbc + 3 * 128  + __byte_perm(pw.x, 0, 0x4443)); \
        unsigned l4  = *(const unsigned*)(tbc + 4 * 128  + __byte_perm(pw.y, 0, 0x4440)); \
        unsigned l5  = *(const unsigned*)(tbc + 5 * 128  + __byte_perm(pw.y, 0, 0x4441)); \
        unsigned l6  = *(const unsigned*)(tbc + 6 * 128  + __byte_perm(pw.y, 0, 0x4442)); \
        unsigned l7  = *(const unsigned*)(tbc + 7 * 128  + __byte_perm(pw.y, 0, 0x4443)); \
        unsigned l8  = *(const unsigned*)(tbc + 8 * 128  + __byte_perm(pw.z, 0, 0x4440)); \
        unsigned l9  = *(const unsigned*)(tbc + 9 * 128  + __byte_perm(pw.z, 0, 0x4441)); \
        unsigned l10 = *(const unsigned*)(tbc + 10 * 128 + __byte_perm(pw.z, 0, 0x4442)); \
        unsigned l11 = *(const unsigned*)(tbc + 11 * 128 + __byte_perm(pw.z, 0, 0x4443)); \
        unsigned l12 = *(const unsigned*)(tbc + 12 * 128 + __byte_perm(pw.w, 0, 0x4440)); \
        unsigned l13 = *(const unsigned*)(tbc + 13 * 128 + __byte_perm(pw.w, 0, 0x4441)); \
        unsigned l14 = *(const unsigned*)(tbc + 14 * 128 + __byte_perm(pw.w, 0, 0x4442)); \
        unsigned l15 = *(const unsigned*)(tbc + 15 * 128 + __byte_perm(pw.w, 0, 0x4443)); \
        unsigned s0, c0, s1, c1, s2, c2, s3, c3, s4, c4;                          \
        fa(l0, l1, l2, s0, c0);                                                   \
        fa(l3, l4, l5, s1, c1);                                                   \
        fa(l6, l7, l8, s2, c2);                                                   \
        fa(l9, l10, l11, s3, c3);                                                 \
        fa(l12, l13, l14, s4, c4);                                                \
        unsigned t0, d0, t1, d1;                                                  \
        fa(s0, s1, s2, t0, d0);                                                   \
        fa(s3, s4, l15, t1, d1);                                                  \
        unsigned n0, e0; ha(t0, t1, n0, e0);                                      \
        unsigned f0, g0, f1, g1, f2, g2;                                          \
        fa(c0, c1, c2, f0, g0);                                                   \
        fa(c3, c4, d0, f1, g1);                                                   \
        fa(f0, f1, d1, f2, g2);                                                   \
        unsigned n1, g3; ha(f2, e0, n1, g3);                                      \
        unsigned h0, k0; fa(g0, g1, g2, h0, k0);                                  \
        unsigned n2, k1; ha(h0, g3, n2, k1);                                      \
        unsigned n3, n4; ha(k0, k1, n3, n4);                                      \
        unsigned gt = n0 & ~mx0;                                                  \
        gt = (n1 & ~mx1) | (~(n1 ^ mx1) & gt);                                    \
        gt = (n2 & ~mx2) | (~(n2 ^ mx2) & gt);                                    \
        gt = (n3 & ~mx3) | (~(n3 ^ mx3) & gt);                                    \
        gt = (n4 & ~mx4) | (~(n4 ^ mx4) & gt);                                    \
        mx0 = (n0 & gt) | (mx0 & ~gt);                                            \
        mx1 = (n1 & gt) | (mx1 & ~gt);                                            \
        mx2 = (n2 & gt) | (mx2 & ~gt);                                            \
        mx3 = (n3 & gt) | (mx3 & ~gt);                                            \
        mx4 = (n4 & gt) | (mx4 & ~gt);                                            \
        if ((I) & 1)  b0 |= gt; else b0 &= ~gt;                                   \
        if ((I) & 2)  b1 |= gt; else b1 &= ~gt;                                   \
        if ((I) & 4)  b2 |= gt; else b2 &= ~gt;                                   \
        if ((I) & 8)  b3 |= gt; else b3 &= ~gt;                                   \
        if ((I) & 16) b4 |= gt; else b4 &= ~gt;                                   \
    } while (0)

    STEP(0);  STEP(1);  STEP(2);  STEP(3);  STEP(4);  STEP(5);
    STEP(6);  STEP(7);  STEP(8);  STEP(9);  STEP(10); STEP(11);
    STEP(12); STEP(13); STEP(14); STEP(15); STEP(16); STEP(17);
    STEP(18); STEP(19); STEP(20); STEP(21); STEP(22); STEP(23);
    if (tid < TAIL) STEP(24);
#undef STEP

    // Materialize full row planes: row = tid (8 bits) | iter (5 bits).
    unsigned mx[5] = {mx0, mx1, mx2, mx3, mx4};
    unsigned bi[13];
#pragma unroll
    for (int p = 0; p < 8; p++) bi[p] = (tid & (1u << p)) ? 0xffffffffu : 0u;
    bi[8] = b0; bi[9] = b1; bi[10] = b2; bi[11] = b3; bi[12] = b4;

    // Warp butterfly merge of (cnt desc, row asc), bit-sliced.
#pragma unroll
    for (int k = 1; k < 32; k <<= 1) {
        unsigned o[5], q[13];
#pragma unroll
        for (int p = 0; p < 5; p++)  o[p] = __shfl_xor_sync(0xffffffffu, mx[p], k);
#pragma unroll
        for (int p = 0; p < 13; p++) q[p] = __shfl_xor_sync(0xffffffffu, bi[p], k);
        unsigned gtc = mx[0] & ~o[0];
#pragma unroll
        for (int p = 1; p < 5; p++)
            gtc = (mx[p] & ~o[p]) | (~(mx[p] ^ o[p]) & gtc);
        unsigned orx = 0;
#pragma unroll
        for (int p = 0; p < 5; p++) orx |= mx[p] ^ o[p];    // ~orx = counts equal
        unsigned lt = ~bi[0] & q[0];
#pragma unroll
        for (int p = 1; p < 13; p++)
            lt = (~bi[p] & q[p]) | (~(bi[p] ^ q[p]) & lt);  // my row < partner row
        unsigned tm = gtc | (lt & ~orx);                    // keep mine
#pragma unroll
        for (int p = 0; p < 5; p++)  mx[p] = (mx[p] & tm) | (o[p] & ~tm);
#pragma unroll
        for (int p = 0; p < 13; p++) bi[p] = (bi[p] & tm) | (q[p] & ~tm);
    }

    // lane q extracts query q's (cnt,row) from the merged planes
    unsigned cnt = 0, lr = 0;
#pragma unroll
    for (int p = 0; p < 5; p++)  cnt |= ((mx[p] >> lane) & 1u) << p;
#pragma unroll
    for (int p = 0; p < 13; p++) lr  |= ((bi[p] >> lane) & 1u) << p;
    unsigned row = rowBase + lr;
    unsigned key = (cnt << 17) | (131071u - row);
    atomicMax(&g_keys[group * 32 + lane], key);
}

// ---------------------------------------------------------------------------
// Kernel 3: gather meanings of the winner, emit one-hot (one thread/query).
// PDL: dtype-detect LDG chain runs pre-wait; g_keys read post-wait.
// ---------------------------------------------------------------------------
__global__ void __launch_bounds__(128) out_kernel(const void* __restrict__ meanv,
                                                  float* __restrict__ out) {
    const int lane = threadIdx.x & 31;
    const int* m32 = (const int*)meanv;
    bool nzd = false;
#pragma unroll
    for (int r = 0; r < 4; r++) nzd |= (m32[(lane * 4 + r) * 2 + 1] != 0);
    const bool m64 = (__ballot_sync(0xffffffffu, nzd) == 0);

    griddep_wait();                               // knn grid done: g_keys final

    const int q = blockIdx.x * blockDim.x + threadIdx.x;   // 0..2047
    if (q >= BATCH) return;
    unsigned key = __ldg(&g_keys[q]);
    int row = 131071 - (int)(key & 0x1FFFFu);

    int m[NTYPES];
#pragma unroll
    for (int t = 0; t < NTYPES; t++)
        m[t] = m64 ? (int)__ldg((const long long*)meanv + (size_t)row * NTYPES + t)
                   : __ldg(m32 + (size_t)row * NTYPES + t);

    float2* o = reinterpret_cast<float2*>(out + (size_t)q * NTYPES * MPT);
#pragma unroll
    for (int e = 0; e < (NTYPES * MPT) / 2; e++) {
        const int e0 = 2 * e, e1 = 2 * e + 1;
        float2 v;
        v.x = (m[e0 / MPT] == e0 % MPT) ? 1.0f : 0.0f;
        v.y = (m[e1 / MPT] == e1 % MPT) ? 1.0f : 0.0f;
        o[e] = v;
    }
}

extern "C" void kernel_launch(void* const* d_in, const int* in_sizes, int n_in,
                              void* d_out, int out_size) {
    const void*  utts     = d_in[0];                 // [16,2048] int64/int32
    const float* support  = (const float*)d_in[1];   // [100000,512] fp32 one-hot
    const void*  meanings = (const void*)d_in[2];    // [100000,5] int64/int32
    float* out = (float*)d_out;                      // [2048,5,10] fp32

    decode_kernel<<<(ENTRIES / 32 + 7) / 8, 256>>>(support);

    // knn with programmatic dependent launch (preamble overlaps decode tail)
    {
        cudaLaunchConfig_t cfg = {};
        cfg.gridDim  = dim3(NS, NGROUPS);            // (16,64) = 1024 blocks
        cfg.blockDim = dim3(TPB);
        cfg.stream   = 0;
        cudaLaunchAttribute a[1];
        a[0].id = cudaLaunchAttributeProgrammaticStreamSerialization;
        a[0].val.programmaticStreamSerializationAllowed = 1;
        cfg.attrs = a;
        cfg.numAttrs = 1;
        cudaLaunchKernelEx(&cfg, knn_kernel, utts);
    }

    // out with programmatic dependent launch (detect chain overlaps knn tail)
    {
        cudaLaunchConfig_t cfg = {};
        cfg.gridDim  = dim3((BATCH + 127) / 128);
        cfg.blockDim = dim3(128);
        cfg.stream   = 0;
        cudaLaunchAttribute a[1];
        a[0].id = cudaLaunchAttributeProgrammaticStreamSerialization;
        a[0].val.programmaticStreamSerializationAllowed = 1;
        cfg.attrs = a;
        cfg.numAttrs = 1;
        cudaLaunchKernelEx(&cfg, out_kernel, meanings, out);
    }
}